// round 6
// baseline (speedup 1.0000x reference)
#include <cuda_runtime.h>

#define NB      4
#define RB      72          // NB * 18 rows per CTA
#define THREADS 512
#define TSTEPS  128
#define NNODE   18
#define DIMX    32
#define HIDN    64
#define STF     132         // feature-buffer row stride (floats), padded
#define STH     68          // hidden-state row stride
#define STX     36          // x-tile row stride
#define NBLK    128         // grid: 512 / NB
#define STS2    24          // St2 row stride in float2

// packed-weight section offsets (floats)
#define GATE0_OFF 0
#define GATE1_OFF 61440
#define CAND0_OFF 143360
#define CAND1_OFF 174080
#define WPK_TOTAL 215040

typedef unsigned long long u64;

__device__ __align__(16) float g_wpk[WPK_TOTAL];

// ---------------- packed f32x2 helpers ----------------
__device__ __forceinline__ u64 pk2(float a, float b) {
    u64 r;
    asm("mov.b64 %0, {%1, %2};" : "=l"(r)
        : "r"(__float_as_uint(a)), "r"(__float_as_uint(b)));
    return r;
}
__device__ __forceinline__ float2 up2(u64 v) {
    unsigned lo, hi;
    asm("mov.b64 {%0, %1}, %2;" : "=r"(lo), "=r"(hi) : "l"(v));
    return make_float2(__uint_as_float(lo), __uint_as_float(hi));
}
__device__ __forceinline__ void fma2(u64 &d, u64 a, u64 b) {
    asm("fma.rn.f32x2 %0, %1, %2, %0;" : "+l"(d) : "l"(a), "l"(b));
}
__device__ __forceinline__ void add2(u64 &d, u64 a) {
    asm("add.rn.f32x2 %0, %0, %1;" : "+l"(d) : "l"(a));
}

__device__ __forceinline__ float sigm(float v) {
    return 1.f / (1.f + __expf(-v));
}
__device__ __forceinline__ float tanh_(float v) {
    float e = __expf(2.f * v);
    return 1.f - 2.f / (e + 1.f);
}

// ---------------- shared memory layout ----------------
struct __align__(16) Smem {
    float2 St2[2][NNODE * STS2]; // transposed supports, duplicated pairs
    float X[RB * STX];          // x tile for current t
    float hA[RB * STH];
    float hB[RB * STH];
    float Z[RB * STF];          // concat input (also aliases reduce scratch)
    float Da[RB * STF];         // Chebyshev x1
    float Db[RB * STF];         // Chebyshev x2
    float OUT[RB * STF];        // gate output (r|u), sigmoided
    float CB[RB * STH];         // candidate output, tanh'd
};
// sizeof = 228096 B  (<= 227 KB dyn-smem limit, 1 CTA/SM)

// ---------------- weight pack kernel ----------------
// gate pack idx = ((((m*2+kh)*G + g)*64 + colg)*4 + kk)*2 + cc
// cand pack idx = ((((m*2+kh)*G + g)*32 + colg)*4 + kk)*2 + cc
__global__ void pack_kernel(const float* __restrict__ wg0,
                            const float* __restrict__ wc0,
                            const float* __restrict__ wg1,
                            const float* __restrict__ wc1)
{
    int i = blockIdx.x * 256 + threadIdx.x;
    if (i >= WPK_TOTAL) return;
    float v;
    if (i < GATE1_OFF) {                     // gate0: CC=96, G=12
        int idx = i;
        int cc = idx & 1, kk = (idx >> 1) & 3, colg = (idx >> 3) & 63;
        int rest = idx >> 9; int g = rest % 12; int r2 = rest / 12;
        int kh = r2 & 1, m = r2 >> 1;
        int k = kh * 48 + 4 * g + kk;
        v = wg0[(m * 96 + k) * 128 + 2 * colg + cc];
    } else if (i < CAND0_OFF) {              // gate1: CC=128, G=16
        int idx = i - GATE1_OFF;
        int cc = idx & 1, kk = (idx >> 1) & 3, colg = (idx >> 3) & 63;
        int rest = idx >> 9; int g = rest % 16; int r2 = rest / 16;
        int kh = r2 & 1, m = r2 >> 1;
        int k = kh * 64 + 4 * g + kk;
        v = wg1[(m * 128 + k) * 128 + 2 * colg + cc];
    } else if (i < CAND1_OFF) {              // cand0: CC=96, G=12
        int idx = i - CAND0_OFF;
        int cc = idx & 1, kk = (idx >> 1) & 3, colg = (idx >> 3) & 31;
        int rest = idx >> 8; int g = rest % 12; int r2 = rest / 12;
        int kh = r2 & 1, m = r2 >> 1;
        int k = kh * 48 + 4 * g + kk;
        v = wc0[(m * 96 + k) * 64 + 2 * colg + cc];
    } else {                                 // cand1: CC=128, G=16
        int idx = i - CAND1_OFF;
        int cc = idx & 1, kk = (idx >> 1) & 3, colg = (idx >> 3) & 31;
        int rest = idx >> 8; int g = rest % 16; int r2 = rest / 16;
        int kh = r2 & 1, m = r2 >> 1;
        int k = kh * 64 + 4 * g + kk;
        v = wc1[(m * 128 + k) * 64 + 2 * colg + cc];
    }
    g_wpk[i] = v;
}

// ---------------- spmm (2 cols/thread): dst = S @ src  (or 2*S@src - Zsub) ----
__device__ __forceinline__ void spmm2(const float2* __restrict__ St,
                                      const float* __restrict__ src,
                                      float* __restrict__ dst,
                                      const float* __restrict__ zsub,
                                      int CC, int rbase, int bloc, int nlo,
                                      int c0)
{
    if (c0 >= CC) return;
    const float* srcb = src + bloc * NNODE * STF + c0;
    u64 a[9];
#pragma unroll
    for (int i = 0; i < 9; i++) a[i] = 0;
#pragma unroll 1
    for (int mm = 0; mm < NNODE; mm++) {
        u64 z = *(const u64*)(srcb + mm * STF);
        const float2* sp = St + mm * STS2 + nlo;
        ulonglong2 p01 = *(const ulonglong2*)(sp);
        ulonglong2 p23 = *(const ulonglong2*)(sp + 2);
        ulonglong2 p45 = *(const ulonglong2*)(sp + 4);
        ulonglong2 p67 = *(const ulonglong2*)(sp + 6);
        u64        p8  = *(const u64*)(sp + 8);
        fma2(a[0], p01.x, z); fma2(a[1], p01.y, z);
        fma2(a[2], p23.x, z); fma2(a[3], p23.y, z);
        fma2(a[4], p45.x, z); fma2(a[5], p45.y, z);
        fma2(a[6], p67.x, z); fma2(a[7], p67.y, z);
        fma2(a[8], p8,    z);
    }
#pragma unroll
    for (int i = 0; i < 9; i++) {
        float2 p = up2(a[i]);
        float2 o;
        if (zsub) {
            float2 zz = *(const float2*)(zsub + (rbase + i) * STF + c0);
            o = make_float2(2.f * p.x - zz.x, 2.f * p.y - zz.y);
        } else {
            o = p;
        }
        *(float2*)(dst + (rbase + i) * STF + c0) = o;
    }
}

// ---------------- pipelined weight chunk ----------------
struct W8 { ulonglong2 a, b; };
__device__ __forceinline__ W8 ldw8(const float* p) {
    W8 w;
    w.a = __ldg((const ulonglong2*)p);
    w.b = __ldg((const ulonglong2*)(p + 4));
    return w;
}

// gate GEMM k-slice: 18 rows x 2 cols per thread, depth-2 W prefetch
template<int CC>
__device__ __forceinline__ void gemm_gate_t(const float* __restrict__ feat,
                                            const float* __restrict__ wq,
                                            int kbeg, int rbase18, u64 acc[18])
{
    constexpr int G = CC / 8;   // (CC/2)/4 groups
    W8 wc = ldw8(wq);
    W8 wn = ldw8(wq + 512);
#pragma unroll 2
    for (int g = 0; g < G; g++) {
        W8 wf = wc;
        if (g + 2 < G) wf = ldw8(wq + (size_t)(g + 2) * 512);
        const float* fp = feat + rbase18 * STF + kbeg + 4 * g;
#pragma unroll
        for (int i = 0; i < 18; i++) {
            float4 f = *(const float4*)(fp + i * STF);
            fma2(acc[i], pk2(f.x, f.x), wc.a.x);
            fma2(acc[i], pk2(f.y, f.y), wc.a.y);
            fma2(acc[i], pk2(f.z, f.z), wc.b.x);
            fma2(acc[i], pk2(f.w, f.w), wc.b.y);
        }
        wc = wn; wn = wf;
    }
}

// cand GEMM k-slice: 9 rows x 2 cols per thread, depth-2 W prefetch
template<int CC>
__device__ __forceinline__ void gemm_cand_t(const float* __restrict__ feat,
                                            const float* __restrict__ wq,
                                            int kbeg, int rbase9, u64 acc[9])
{
    constexpr int G = CC / 8;
    W8 wc = ldw8(wq);
    W8 wn = ldw8(wq + 256);
#pragma unroll 2
    for (int g = 0; g < G; g++) {
        W8 wf = wc;
        if (g + 2 < G) wf = ldw8(wq + (size_t)(g + 2) * 256);
        const float* fp = feat + rbase9 * STF + kbeg + 4 * g;
#pragma unroll
        for (int i = 0; i < 9; i++) {
            float4 f = *(const float4*)(fp + i * STF);
            fma2(acc[i], pk2(f.x, f.x), wc.a.x);
            fma2(acc[i], pk2(f.y, f.y), wc.a.y);
            fma2(acc[i], pk2(f.z, f.z), wc.b.x);
            fma2(acc[i], pk2(f.w, f.w), wc.b.y);
        }
        wc = wn; wn = wf;
    }
}

// ---------------- per-cell body ----------------
template<int CELL>
__device__ __forceinline__ void cell_body(
    Smem& sm,
    const float* __restrict__ BG, const float* __restrict__ BC,
    int tid)
{
    constexpr int CC  = CELL ? 128 : 96;
    constexpr int CCH = CC / 2;
    constexpr int G   = CC / 8;
    const float* wgp = g_wpk + (CELL ? GATE1_OFF : GATE0_OFF);
    const float* wcp = g_wpk + (CELL ? CAND1_OFF : CAND0_OFF);
    float* H = CELL ? sm.hB : sm.hA;

    // gemm thread maps
    const int khalf   = tid >> 8;
    const int kbeg    = khalf * CCH;
    const int rowg_g  = tid & 3;            // gate: 4 groups of 18 rows
    const int colg_g  = (tid >> 2) & 63;
    const int rbase18 = 18 * rowg_g;
    const int rowg_c  = tid & 7;            // cand: 8 groups of 9 rows
    const int colg_c  = (tid >> 3) & 31;
    const int rbase9  = 9 * rowg_c;
    // spmm thread map
    const int rowg_s  = tid & 7;
    const int c0      = 2 * (tid >> 3);
    const int rbase_s = 9 * rowg_s;
    const int bloc_s  = rowg_s >> 1;
    const int nlo_s   = (rowg_s & 1) ? 12 : 0;

    u64* const scr = (u64*)sm.Z;            // reduce scratch aliases Z

    // ============ GATE dconv ============
    if (CELL == 0) {
        for (int j = tid; j < RB * 24; j += THREADS) {
            int r = j / 24, c = 4 * (j - 24 * r);
            float4 v = (c < DIMX)
                ? *(const float4*)(sm.X + r * STX + c)
                : *(const float4*)(sm.hA + r * STH + (c - DIMX));
            *(float4*)(sm.Z + r * STF + c) = v;
        }
    } else {
        for (int j = tid; j < RB * 32; j += THREADS) {
            int r = j >> 5, c = 4 * (j & 31);
            float4 v = (c < HIDN)
                ? *(const float4*)(sm.hA + r * STH + c)
                : *(const float4*)(sm.hB + r * STH + (c - HIDN));
            *(float4*)(sm.Z + r * STF + c) = v;
        }
    }
    __syncthreads();

    {
        u64 ga[18];
#pragma unroll
        for (int q = 0; q < 18; q++) ga[q] = 0;
#pragma unroll 1
        for (int m = 0; m < 5; m++) {
            const float* feat;
            if (m == 0) feat = sm.Z;
            else {
                int s = (m - 1) >> 1;
                int second = (m - 1) & 1;
                const float* src = second ? sm.Da : sm.Z;
                float* dst = second ? sm.Db : sm.Da;
                spmm2(sm.St2[s], src, dst, second ? sm.Z : (const float*)0,
                      CC, rbase_s, bloc_s, nlo_s, c0);
                __syncthreads();
                feat = dst;
            }
            gemm_gate_t<CC>(feat,
                            wgp + ((size_t)(m * 2 + khalf) * G * 64 + colg_g) * 8,
                            kbeg, rbase18, ga);
        }
        __syncthreads();
        if (khalf) {
            u64* s = scr + (size_t)(tid - 256) * 18;
#pragma unroll
            for (int q = 0; q < 18; q++) s[q] = ga[q];
        }
        __syncthreads();
        if (!khalf) {
            const u64* s = scr + (size_t)tid * 18;
#pragma unroll
            for (int q = 0; q < 18; q++) add2(ga[q], s[q]);
            float2 bv = *(const float2*)(BG + 2 * colg_g);
#pragma unroll
            for (int i = 0; i < 18; i++) {
                float2 p = up2(ga[i]);
                float2 o = make_float2(sigm(p.x + bv.x), sigm(p.y + bv.y));
                *(float2*)(sm.OUT + (rbase18 + i) * STF + 2 * colg_g) = o;
            }
        }
    }
    __syncthreads();

    // ============ CANDIDATE dconv ============
    if (CELL == 0) {
        for (int j = tid; j < RB * 24; j += THREADS) {
            int r = j / 24, c = 4 * (j - 24 * r);
            float4 v;
            if (c < DIMX) {
                v = *(const float4*)(sm.X + r * STX + c);
            } else {
                float4 h4 = *(const float4*)(sm.hA + r * STH + (c - DIMX));
                float4 rr = *(const float4*)(sm.OUT + r * STF + (c - DIMX));
                v = make_float4(h4.x * rr.x, h4.y * rr.y,
                                h4.z * rr.z, h4.w * rr.w);
            }
            *(float4*)(sm.Z + r * STF + c) = v;
        }
    } else {
        for (int j = tid; j < RB * 32; j += THREADS) {
            int r = j >> 5, c = 4 * (j & 31);
            float4 v;
            if (c < HIDN) {
                v = *(const float4*)(sm.hA + r * STH + c);
            } else {
                float4 h4 = *(const float4*)(sm.hB + r * STH + (c - HIDN));
                float4 rr = *(const float4*)(sm.OUT + r * STF + (c - HIDN));
                v = make_float4(h4.x * rr.x, h4.y * rr.y,
                                h4.z * rr.z, h4.w * rr.w);
            }
            *(float4*)(sm.Z + r * STF + c) = v;
        }
    }
    __syncthreads();

    {
        u64 ca[9];
#pragma unroll
        for (int q = 0; q < 9; q++) ca[q] = 0;
#pragma unroll 1
        for (int m = 0; m < 5; m++) {
            const float* feat;
            if (m == 0) feat = sm.Z;
            else {
                int s = (m - 1) >> 1;
                int second = (m - 1) & 1;
                const float* src = second ? sm.Da : sm.Z;
                float* dst = second ? sm.Db : sm.Da;
                spmm2(sm.St2[s], src, dst, second ? sm.Z : (const float*)0,
                      CC, rbase_s, bloc_s, nlo_s, c0);
                __syncthreads();
                feat = dst;
            }
            gemm_cand_t<CC>(feat,
                            wcp + ((size_t)(m * 2 + khalf) * G * 32 + colg_c) * 8,
                            kbeg, rbase9, ca);
        }
        __syncthreads();
        if (khalf) {
            u64* s = scr + (size_t)(tid - 256) * 9;
#pragma unroll
            for (int q = 0; q < 9; q++) s[q] = ca[q];
        }
        __syncthreads();
        if (!khalf) {
            const u64* s = scr + (size_t)tid * 9;
#pragma unroll
            for (int q = 0; q < 9; q++) add2(ca[q], s[q]);
            float2 bv = *(const float2*)(BC + 2 * colg_c);
#pragma unroll
            for (int i = 0; i < 9; i++) {
                float2 p = up2(ca[i]);
                float2 o = make_float2(tanh_(p.x + bv.x), tanh_(p.y + bv.y));
                *(float2*)(sm.CB + (rbase9 + i) * STH + 2 * colg_c) = o;
            }
        }
    }
    __syncthreads();

    // ============ GRU update: h = c + u*(h - c) ============
    for (int j = tid; j < RB * 32; j += THREADS) {
        int r = j >> 5, c = 2 * (j & 31);
        float2 h2 = *(const float2*)(H + r * STH + c);
        float2 c2 = *(const float2*)(sm.CB + r * STH + c);
        float2 u2 = *(const float2*)(sm.OUT + r * STF + HIDN + c);
        float2 nh = make_float2(c2.x + u2.x * (h2.x - c2.x),
                                c2.y + u2.y * (h2.y - c2.y));
        *(float2*)(H + r * STH + c) = nh;
    }
    __syncthreads();
}

// ---------------- main persistent kernel ----------------
__global__ void __launch_bounds__(THREADS, 1)
dcrnn_kernel(const float* __restrict__ x,   const float* __restrict__ sup,
             const float* __restrict__ bg0, const float* __restrict__ bc0,
             const float* __restrict__ bg1, const float* __restrict__ bc1,
             const float* __restrict__ fcw, const float* __restrict__ fcb,
             float* __restrict__ out)
{
    extern __shared__ char smraw[];
    Smem& sm = *reinterpret_cast<Smem*>(smraw);

    const int tid   = threadIdx.x;
    const int bbase = blockIdx.x * NB;

    // init: transpose + duplicate supports into St2
    for (int i = tid; i < 2 * NNODE * NNODE; i += THREADS) {
        int s = i / (NNODE * NNODE);
        int rem = i - s * NNODE * NNODE;
        int n = rem / NNODE;              // row of S
        int m = rem - n * NNODE;          // col of S
        float v = sup[i];
        int lane = (n < 9) ? n : (12 + n - 9);
        sm.St2[s][m * STS2 + lane] = make_float2(v, v);
    }
    for (int i = tid; i < RB * STH; i += THREADS) { sm.hA[i] = 0.f; sm.hB[i] = 0.f; }
    __syncthreads();

    for (int t = 0; t < TSTEPS; t++) {
        // ---- load x tile: X[r][0:32] = x[b, t, n, :] ----
        for (int j = tid; j < RB * 8; j += THREADS) {
            int r = j >> 3, d4 = j & 7;
            int b = bbase + r / NNODE;
            int n = r - NNODE * (r / NNODE);
            float4 v = *(const float4*)(x +
                (((size_t)b * TSTEPS + t) * NNODE + n) * DIMX + 4 * d4);
            *(float4*)(sm.X + r * STX + 4 * d4) = v;
        }
        __syncthreads();

        cell_body<0>(sm, bg0, bc0, tid);
        cell_body<1>(sm, bg1, bc1, tid);
    }

    // ---- epilogue: logits = relu(hB) @ fc_w + fc_b; out[b] = max over nodes ----
    if (tid < RB) {
        float acc = fcb[0];
#pragma unroll
        for (int c = 0; c < HIDN; c++)
            acc += fmaxf(sm.hB[tid * STH + c], 0.f) * fcw[c];
        sm.Da[tid] = acc;
    }
    __syncthreads();
    if (tid < NB) {
        float mx = -3.4e38f;
#pragma unroll
        for (int n = 0; n < NNODE; n++)
            mx = fmaxf(mx, sm.Da[tid * NNODE + n]);
        out[bbase + tid] = mx;
    }
}

extern "C" void kernel_launch(void* const* d_in, const int* in_sizes, int n_in,
                              void* d_out, int out_size)
{
    (void)in_sizes; (void)n_in; (void)out_size;
    const size_t shbytes = sizeof(Smem);
    cudaFuncSetAttribute(dcrnn_kernel,
                         cudaFuncAttributeMaxDynamicSharedMemorySize,
                         (int)shbytes);
    // repack weights into per-thread consumption order
    pack_kernel<<<(WPK_TOTAL + 255) / 256, 256>>>(
        (const float*)d_in[2],  (const float*)d_in[4],
        (const float*)d_in[6],  (const float*)d_in[8]);
    dcrnn_kernel<<<NBLK, THREADS, shbytes>>>(
        (const float*)d_in[0],  (const float*)d_in[1],
        (const float*)d_in[3],  (const float*)d_in[5],
        (const float*)d_in[7],  (const float*)d_in[9],
        (const float*)d_in[10], (const float*)d_in[11],
        (float*)d_out);
}

// round 7
// speedup vs baseline: 1.2896x; 1.2896x over previous
#include <cuda_runtime.h>

#define NB      4
#define RB      72          // NB * 18 rows per CTA
#define THREADS 256
#define TSTEPS  128
#define NNODE   18
#define DIMX    32
#define HIDN    64
#define STF     132         // feature-buffer row stride (floats), padded
#define STH     68          // hidden-state row stride
#define STX     36          // x-tile row stride
#define NBLK    128         // grid: 512 / NB
#define STS2    24          // St2 row stride in float2

typedef unsigned long long u64;

// ---------------- packed f32x2 helpers ----------------
__device__ __forceinline__ u64 pk2(float a, float b) {
    u64 r;
    asm("mov.b64 %0, {%1, %2};" : "=l"(r)
        : "r"(__float_as_uint(a)), "r"(__float_as_uint(b)));
    return r;
}
__device__ __forceinline__ float2 up2(u64 v) {
    unsigned lo, hi;
    asm("mov.b64 {%0, %1}, %2;" : "=r"(lo), "=r"(hi) : "l"(v));
    return make_float2(__uint_as_float(lo), __uint_as_float(hi));
}
__device__ __forceinline__ void fma2(u64 &d, u64 a, u64 b) {
    asm("fma.rn.f32x2 %0, %1, %2, %0;" : "+l"(d) : "l"(a), "l"(b));
}
__device__ __forceinline__ void add2(u64 &d, u64 a) {
    asm("add.rn.f32x2 %0, %0, %1;" : "+l"(d) : "l"(a));
}

__device__ __forceinline__ float sigm(float v) {
    return 1.f / (1.f + __expf(-v));
}
__device__ __forceinline__ float tanh_(float v) {
    float e = __expf(2.f * v);
    return 1.f - 2.f / (e + 1.f);
}

// ---------------- shared memory layout ----------------
struct __align__(16) Smem {
    float2 St2[2][NNODE * STS2]; // transposed supports, duplicated pairs
    float X[RB * STX];          // x tile for current t
    float hA[RB * STH];
    float hB[RB * STH];
    float Z[RB * STF];          // concat input (aliases reduce scratch)
    float Da[RB * STF];         // Chebyshev x1
    float Db[RB * STF];         // Chebyshev x2
    float OUT[RB * STF];        // gate output (r|u), sigmoided
    float CB[RB * STH];         // candidate output, tanh'd
};
// sizeof = 228096 B  (<= 227 KB dyn-smem limit, 1 CTA/SM)

// ---------------- spmm (4 cols/thread): dst = S @ src  (or 2*S@src - Zsub) ----
__device__ __forceinline__ void spmm4(const float2* __restrict__ St,
                                      const float* __restrict__ src,
                                      float* __restrict__ dst,
                                      const float* __restrict__ zsub,
                                      int CC, int rbase, int bloc, int nlo,
                                      int c0)
{
    if (c0 >= CC) return;
    const float* srcb = src + bloc * NNODE * STF + c0;
    u64 a[18];
#pragma unroll
    for (int i = 0; i < 18; i++) a[i] = 0;
#pragma unroll 1
    for (int mm = 0; mm < NNODE; mm++) {
        ulonglong2 z = *(const ulonglong2*)(srcb + mm * STF);
        const float2* sp = St + mm * STS2 + nlo;
        ulonglong2 p01 = *(const ulonglong2*)(sp);
        ulonglong2 p23 = *(const ulonglong2*)(sp + 2);
        ulonglong2 p45 = *(const ulonglong2*)(sp + 4);
        ulonglong2 p67 = *(const ulonglong2*)(sp + 6);
        u64        p8  = *(const u64*)(sp + 8);
        fma2(a[0],  p01.x, z.x); fma2(a[1],  p01.x, z.y);
        fma2(a[2],  p01.y, z.x); fma2(a[3],  p01.y, z.y);
        fma2(a[4],  p23.x, z.x); fma2(a[5],  p23.x, z.y);
        fma2(a[6],  p23.y, z.x); fma2(a[7],  p23.y, z.y);
        fma2(a[8],  p45.x, z.x); fma2(a[9],  p45.x, z.y);
        fma2(a[10], p45.y, z.x); fma2(a[11], p45.y, z.y);
        fma2(a[12], p67.x, z.x); fma2(a[13], p67.x, z.y);
        fma2(a[14], p67.y, z.x); fma2(a[15], p67.y, z.y);
        fma2(a[16], p8,    z.x); fma2(a[17], p8,    z.y);
    }
#pragma unroll
    for (int i = 0; i < 9; i++) {
        float2 q0 = up2(a[2 * i]), q1 = up2(a[2 * i + 1]);
        float4 o;
        if (zsub) {
            float4 zz = *(const float4*)(zsub + (rbase + i) * STF + c0);
            o = make_float4(2.f * q0.x - zz.x, 2.f * q0.y - zz.y,
                            2.f * q1.x - zz.z, 2.f * q1.y - zz.w);
        } else {
            o = make_float4(q0.x, q0.y, q1.x, q1.y);
        }
        *(float4*)(dst + (rbase + i) * STF + c0) = o;
    }
}

// ---------------- W loaders ----------------
__device__ __forceinline__ void ldwg(const float* p, ulonglong2 w[8]) {
#pragma unroll
    for (int kk = 0; kk < 4; kk++) {
        w[2 * kk]     = __ldg((const ulonglong2*)(p + kk * 128));
        w[2 * kk + 1] = __ldg((const ulonglong2*)(p + kk * 128 + 4));
    }
}
__device__ __forceinline__ void ldwc(const float* p, ulonglong2 w[4]) {
#pragma unroll
    for (int kk = 0; kk < 4; kk++)
        w[kk] = __ldg((const ulonglong2*)(p + kk * 64));
}

// gate GEMM k-slice: 9 rows x 8 cols per thread (16 fma2 per feat LDS.128)
template<int CC>
__device__ __forceinline__ void gemm_gate(const float* __restrict__ feat,
                                          const float* __restrict__ W,
                                          int kbeg, int c8, int rbase,
                                          u64 acc[36])
{
    constexpr int G = CC / 8;   // 4-k groups in this k-half
    const float* wp = W + (size_t)kbeg * 128 + c8;
    ulonglong2 wc[8], wn[8];
    ldwg(wp, wc);
#pragma unroll 2
    for (int g = 0; g < G; g++) {
        if (g + 1 < G) ldwg(wp + (size_t)(g + 1) * 512, wn);
        const float* fp = feat + rbase * STF + kbeg + 4 * g;
#pragma unroll
        for (int i = 0; i < 9; i++) {
            float4 f = *(const float4*)(fp + i * STF);
            u64 f0 = pk2(f.x, f.x), f1 = pk2(f.y, f.y);
            u64 f2 = pk2(f.z, f.z), f3 = pk2(f.w, f.w);
            fma2(acc[4 * i + 0], f0, wc[0].x); fma2(acc[4 * i + 1], f0, wc[0].y);
            fma2(acc[4 * i + 2], f0, wc[1].x); fma2(acc[4 * i + 3], f0, wc[1].y);
            fma2(acc[4 * i + 0], f1, wc[2].x); fma2(acc[4 * i + 1], f1, wc[2].y);
            fma2(acc[4 * i + 2], f1, wc[3].x); fma2(acc[4 * i + 3], f1, wc[3].y);
            fma2(acc[4 * i + 0], f2, wc[4].x); fma2(acc[4 * i + 1], f2, wc[4].y);
            fma2(acc[4 * i + 2], f2, wc[5].x); fma2(acc[4 * i + 3], f2, wc[5].y);
            fma2(acc[4 * i + 0], f3, wc[6].x); fma2(acc[4 * i + 1], f3, wc[6].y);
            fma2(acc[4 * i + 2], f3, wc[7].x); fma2(acc[4 * i + 3], f3, wc[7].y);
        }
#pragma unroll
        for (int q = 0; q < 8; q++) wc[q] = wn[q];
    }
}

// cand GEMM k-slice: 9 rows x 4 cols per thread
template<int CC>
__device__ __forceinline__ void gemm_cand(const float* __restrict__ feat,
                                          const float* __restrict__ W,
                                          int kbeg, int c4, int rbase,
                                          u64 acc[18])
{
    constexpr int G = CC / 8;
    const float* wp = W + (size_t)kbeg * 64 + c4;
    ulonglong2 wc[4], wn[4];
    ldwc(wp, wc);
#pragma unroll 2
    for (int g = 0; g < G; g++) {
        if (g + 1 < G) ldwc(wp + (size_t)(g + 1) * 256, wn);
        const float* fp = feat + rbase * STF + kbeg + 4 * g;
#pragma unroll
        for (int i = 0; i < 9; i++) {
            float4 f = *(const float4*)(fp + i * STF);
            fma2(acc[2 * i], pk2(f.x, f.x), wc[0].x);
            fma2(acc[2 * i + 1], pk2(f.x, f.x), wc[0].y);
            fma2(acc[2 * i], pk2(f.y, f.y), wc[1].x);
            fma2(acc[2 * i + 1], pk2(f.y, f.y), wc[1].y);
            fma2(acc[2 * i], pk2(f.z, f.z), wc[2].x);
            fma2(acc[2 * i + 1], pk2(f.z, f.z), wc[2].y);
            fma2(acc[2 * i], pk2(f.w, f.w), wc[3].x);
            fma2(acc[2 * i + 1], pk2(f.w, f.w), wc[3].y);
        }
#pragma unroll
        for (int q = 0; q < 4; q++) wc[q] = wn[q];
    }
}

// ---------------- main persistent kernel ----------------
__global__ void __launch_bounds__(THREADS, 1)
dcrnn_kernel(const float* __restrict__ x,   const float* __restrict__ sup,
             const float* __restrict__ wg0, const float* __restrict__ bg0,
             const float* __restrict__ wc0, const float* __restrict__ bc0,
             const float* __restrict__ wg1, const float* __restrict__ bg1,
             const float* __restrict__ wc1, const float* __restrict__ bc1,
             const float* __restrict__ fcw, const float* __restrict__ fcb,
             float* __restrict__ out)
{
    extern __shared__ char smraw[];
    Smem& sm = *reinterpret_cast<Smem*>(smraw);

    const int tid   = threadIdx.x;
    const int bbase = blockIdx.x * NB;
    const int rowg  = tid & 7;            // 8 row groups of 9 rows
    const int colg  = (tid >> 3) & 15;    // 16 col groups
    const int khalf = tid >> 7;           // k-slice half
    const int c8    = 8 * colg;           // gate col base
    const int c4    = 4 * colg;           // cand col base
    const int c0    = 4 * colg + 64 * khalf;  // spmm col base (covers 0..124)
    const int rbase = rowg * 9;
    const int bloc  = rowg >> 1;          // local batch of this thread's rows
    const int nlo   = (rowg & 1) ? 12 : 0; // St2 lane base

    u64* const scr = (u64*)sm.Z;          // reduce scratch aliases Z

    // init: transpose + duplicate supports into St2
    for (int i = tid; i < 2 * NNODE * NNODE; i += THREADS) {
        int s = i / (NNODE * NNODE);
        int rem = i - s * NNODE * NNODE;
        int n = rem / NNODE;              // row of S
        int m = rem - n * NNODE;          // col of S
        float v = sup[i];
        int lane = (n < 9) ? n : (12 + n - 9);
        sm.St2[s][m * STS2 + lane] = make_float2(v, v);
    }
    for (int i = tid; i < RB * STH; i += THREADS) { sm.hA[i] = 0.f; sm.hB[i] = 0.f; }
    __syncthreads();

    for (int t = 0; t < TSTEPS; t++) {
        // ---- load x tile: X[r][0:32] = x[b, t, n, :] ----
        for (int j = tid; j < RB * 8; j += THREADS) {
            int r = j >> 3, d4 = j & 7;
            int b = bbase + r / NNODE;
            int n = r - NNODE * (r / NNODE);
            float4 v = *(const float4*)(x +
                (((size_t)b * TSTEPS + t) * NNODE + n) * DIMX + 4 * d4);
            *(float4*)(sm.X + r * STX + 4 * d4) = v;
        }
        __syncthreads();

        for (int cell = 0; cell < 2; cell++) {
            const int CC  = cell ? 128 : 96;
            const int CCH = CC >> 1;
            const int kbeg = khalf * CCH;
            const float* WG = cell ? wg1 : wg0;
            const float* BG = cell ? bg1 : bg0;
            const float* WC = cell ? wc1 : wc0;
            const float* BC = cell ? bc1 : bc0;
            float* H = cell ? sm.hB : sm.hA;

            // ============ GATE dconv ============
            if (cell == 0) {
                for (int j = tid; j < RB * 24; j += THREADS) {
                    int r = j / 24, c = 4 * (j - 24 * r);
                    float4 v = (c < DIMX)
                        ? *(const float4*)(sm.X + r * STX + c)
                        : *(const float4*)(sm.hA + r * STH + (c - DIMX));
                    *(float4*)(sm.Z + r * STF + c) = v;
                }
            } else {
                for (int j = tid; j < RB * 32; j += THREADS) {
                    int r = j >> 5, c = 4 * (j & 31);
                    float4 v = (c < HIDN)
                        ? *(const float4*)(sm.hA + r * STH + c)
                        : *(const float4*)(sm.hB + r * STH + (c - HIDN));
                    *(float4*)(sm.Z + r * STF + c) = v;
                }
            }
            __syncthreads();

            {
                u64 ga[36];
#pragma unroll
                for (int q = 0; q < 36; q++) ga[q] = 0;
#pragma unroll 1
                for (int m = 0; m < 5; m++) {
                    const float* feat;
                    if (m == 0) feat = sm.Z;
                    else {
                        int s = (m - 1) >> 1;
                        int second = (m - 1) & 1;
                        const float* src = second ? sm.Da : sm.Z;
                        float* dst = second ? sm.Db : sm.Da;
                        spmm4(sm.St2[s], src, dst,
                              second ? sm.Z : (const float*)0,
                              CC, rbase, bloc, nlo, c0);
                        __syncthreads();
                        feat = dst;
                    }
                    if (cell) gemm_gate<128>(feat, WG + (size_t)m * 128 * 128,
                                             kbeg, c8, rbase, ga);
                    else      gemm_gate<96> (feat, WG + (size_t)m * 96 * 128,
                                             kbeg, c8, rbase, ga);
                }
                // reduce k-halves via scratch (aliases Z, now dead)
                __syncthreads();
                if (khalf) {
                    u64* s = scr + (size_t)(tid - 128) * 36;
#pragma unroll
                    for (int q = 0; q < 36; q++) s[q] = ga[q];
                }
                __syncthreads();
                if (!khalf) {
                    const u64* s = scr + (size_t)tid * 36;
#pragma unroll
                    for (int q = 0; q < 36; q++) add2(ga[q], s[q]);
                    float4 b0 = *(const float4*)(BG + c8);
                    float4 b1 = *(const float4*)(BG + c8 + 4);
#pragma unroll
                    for (int i = 0; i < 9; i++) {
                        float2 q0 = up2(ga[4 * i]),     q1 = up2(ga[4 * i + 1]);
                        float2 q2 = up2(ga[4 * i + 2]), q3 = up2(ga[4 * i + 3]);
                        float4 o0 = make_float4(sigm(q0.x + b0.x), sigm(q0.y + b0.y),
                                                sigm(q1.x + b0.z), sigm(q1.y + b0.w));
                        float4 o1 = make_float4(sigm(q2.x + b1.x), sigm(q2.y + b1.y),
                                                sigm(q3.x + b1.z), sigm(q3.y + b1.w));
                        *(float4*)(sm.OUT + (rbase + i) * STF + c8)     = o0;
                        *(float4*)(sm.OUT + (rbase + i) * STF + c8 + 4) = o1;
                    }
                }
            }
            __syncthreads();

            // ============ CANDIDATE dconv ============
            if (cell == 0) {
                for (int j = tid; j < RB * 24; j += THREADS) {
                    int r = j / 24, c = 4 * (j - 24 * r);
                    float4 v;
                    if (c < DIMX) {
                        v = *(const float4*)(sm.X + r * STX + c);
                    } else {
                        float4 h4 = *(const float4*)(sm.hA + r * STH + (c - DIMX));
                        float4 rr = *(const float4*)(sm.OUT + r * STF + (c - DIMX));
                        v = make_float4(h4.x * rr.x, h4.y * rr.y,
                                        h4.z * rr.z, h4.w * rr.w);
                    }
                    *(float4*)(sm.Z + r * STF + c) = v;
                }
            } else {
                for (int j = tid; j < RB * 32; j += THREADS) {
                    int r = j >> 5, c = 4 * (j & 31);
                    float4 v;
                    if (c < HIDN) {
                        v = *(const float4*)(sm.hA + r * STH + c);
                    } else {
                        float4 h4 = *(const float4*)(sm.hB + r * STH + (c - HIDN));
                        float4 rr = *(const float4*)(sm.OUT + r * STF + (c - HIDN));
                        v = make_float4(h4.x * rr.x, h4.y * rr.y,
                                        h4.z * rr.z, h4.w * rr.w);
                    }
                    *(float4*)(sm.Z + r * STF + c) = v;
                }
            }
            __syncthreads();

            {
                u64 ca[18];
#pragma unroll
                for (int q = 0; q < 18; q++) ca[q] = 0;
#pragma unroll 1
                for (int m = 0; m < 5; m++) {
                    const float* feat;
                    if (m == 0) feat = sm.Z;
                    else {
                        int s = (m - 1) >> 1;
                        int second = (m - 1) & 1;
                        const float* src = second ? sm.Da : sm.Z;
                        float* dst = second ? sm.Db : sm.Da;
                        spmm4(sm.St2[s], src, dst,
                              second ? sm.Z : (const float*)0,
                              CC, rbase, bloc, nlo, c0);
                        __syncthreads();
                        feat = dst;
                    }
                    if (cell) gemm_cand<128>(feat, WC + (size_t)m * 128 * 64,
                                             kbeg, c4, rbase, ca);
                    else      gemm_cand<96> (feat, WC + (size_t)m * 96 * 64,
                                             kbeg, c4, rbase, ca);
                }
                __syncthreads();
                if (khalf) {
                    u64* s = scr + (size_t)(tid - 128) * 18;
#pragma unroll
                    for (int q = 0; q < 18; q++) s[q] = ca[q];
                }
                __syncthreads();
                if (!khalf) {
                    const u64* s = scr + (size_t)tid * 18;
#pragma unroll
                    for (int q = 0; q < 18; q++) add2(ca[q], s[q]);
                    float4 bv = *(const float4*)(BC + c4);
#pragma unroll
                    for (int i = 0; i < 9; i++) {
                        float2 q0 = up2(ca[2 * i]), q1 = up2(ca[2 * i + 1]);
                        float4 o = make_float4(tanh_(q0.x + bv.x), tanh_(q0.y + bv.y),
                                               tanh_(q1.x + bv.z), tanh_(q1.y + bv.w));
                        *(float4*)(sm.CB + (rbase + i) * STH + c4) = o;
                    }
                }
            }
            __syncthreads();

            // ============ GRU update: h = c + u*(h - c) ============
            for (int j = tid; j < RB * 32; j += THREADS) {
                int r = j >> 5, c = 2 * (j & 31);
                float2 h2 = *(const float2*)(H + r * STH + c);
                float2 c2 = *(const float2*)(sm.CB + r * STH + c);
                float2 u2 = *(const float2*)(sm.OUT + r * STF + HIDN + c);
                float2 nh = make_float2(c2.x + u2.x * (h2.x - c2.x),
                                        c2.y + u2.y * (h2.y - c2.y));
                *(float2*)(H + r * STH + c) = nh;
            }
            __syncthreads();
        } // cell
    } // t

    // ---- epilogue: logits = relu(hB) @ fc_w + fc_b; out[b] = max over nodes ----
    if (tid < RB) {
        float acc = fcb[0];
#pragma unroll
        for (int c = 0; c < HIDN; c++)
            acc += fmaxf(sm.hB[tid * STH + c], 0.f) * fcw[c];
        sm.Da[tid] = acc;
    }
    __syncthreads();
    if (tid < NB) {
        float mx = -3.4e38f;
#pragma unroll
        for (int n = 0; n < NNODE; n++)
            mx = fmaxf(mx, sm.Da[tid * NNODE + n]);
        out[bbase + tid] = mx;
    }
}

extern "C" void kernel_launch(void* const* d_in, const int* in_sizes, int n_in,
                              void* d_out, int out_size)
{
    (void)in_sizes; (void)n_in; (void)out_size;
    const size_t shbytes = sizeof(Smem);
    cudaFuncSetAttribute(dcrnn_kernel,
                         cudaFuncAttributeMaxDynamicSharedMemorySize,
                         (int)shbytes);
    dcrnn_kernel<<<NBLK, THREADS, shbytes>>>(
        (const float*)d_in[0],  (const float*)d_in[1],
        (const float*)d_in[2],  (const float*)d_in[3],
        (const float*)d_in[4],  (const float*)d_in[5],
        (const float*)d_in[6],  (const float*)d_in[7],
        (const float*)d_in[8],  (const float*)d_in[9],
        (const float*)d_in[10], (const float*)d_in[11],
        (float*)d_out);
}